// round 7
// baseline (speedup 1.0000x reference)
#include <cuda_runtime.h>
#include <cuda_bf16.h>
#include <cstdint>

#define FDIM 128
#define MAXN 100000
#define MAXE 1600000
#define SEG 1024
#define MAXSEG 128

// ---------------------------------------------------------------------------
// Scratch
// ---------------------------------------------------------------------------
__device__ int   g_cnt[MAXN];
__device__ int   g_off[MAXN + 1];
__device__ int   g_cur[MAXN];
__device__ int   g_bsum[MAXSEG];
__device__ int   g_esrc[MAXE];
__device__ float g_eval[MAXE];

// ---------------------------------------------------------------------------
// Zero counts
// ---------------------------------------------------------------------------
__global__ void zero_cnt_kernel(int N) {
    int i = blockIdx.x * blockDim.x + threadIdx.x;
    if (i < N) g_cnt[i] = 0;
}

// ---------------------------------------------------------------------------
// Histogram of dst
// ---------------------------------------------------------------------------
__global__ void hist_kernel(const int* __restrict__ dst, int E) {
    int e = blockIdx.x * blockDim.x + threadIdx.x;
    if (e < E) atomicAdd(&g_cnt[dst[e]], 1);
}

// ---------------------------------------------------------------------------
// Scan stage 1: per-segment sums
// ---------------------------------------------------------------------------
__global__ void __launch_bounds__(256) scan1_kernel(int N) {
    __shared__ int ssum[256];
    int t = threadIdx.x;
    int base = blockIdx.x * SEG + t * 4;
    int s = 0;
#pragma unroll
    for (int j = 0; j < 4; ++j) {
        int idx = base + j;
        if (idx < N) s += g_cnt[idx];
    }
    ssum[t] = s;
    __syncthreads();
#pragma unroll
    for (int off = 128; off > 0; off >>= 1) {
        if (t < off) ssum[t] += ssum[t + off];
        __syncthreads();
    }
    if (t == 0) g_bsum[blockIdx.x] = ssum[0];
}

// ---------------------------------------------------------------------------
// Scan stage 3 (scan2 folded in): every block scans segment sums locally.
// ---------------------------------------------------------------------------
__global__ void __launch_bounds__(256) scan3_kernel(int N, int E, int nseg) {
    __shared__ int ssum[256];
    __shared__ int sbs[MAXSEG];
    int t = threadIdx.x;

    if (t < MAXSEG) sbs[t] = (t < nseg) ? g_bsum[t] : 0;
    __syncthreads();
#pragma unroll
    for (int off = 1; off < MAXSEG; off <<= 1) {
        int x = 0;
        if (t < MAXSEG && t >= off) x = sbs[t - off];
        __syncthreads();
        if (t < MAXSEG) sbs[t] += x;
        __syncthreads();
    }
    int blockPrefix = (blockIdx.x == 0) ? 0 : sbs[blockIdx.x - 1];

    int base = blockIdx.x * SEG + t * 4;
    int c[4];
    int tsum = 0;
#pragma unroll
    for (int j = 0; j < 4; ++j) {
        int idx = base + j;
        c[j] = (idx < N) ? g_cnt[idx] : 0;
        tsum += c[j];
    }
    ssum[t] = tsum;
    __syncthreads();
#pragma unroll
    for (int off = 1; off < 256; off <<= 1) {
        int x = (t >= off) ? ssum[t - off] : 0;
        __syncthreads();
        ssum[t] += x;
        __syncthreads();
    }
    int excl = ssum[t] - tsum;
    int pos = blockPrefix + excl;
#pragma unroll
    for (int j = 0; j < 4; ++j) {
        int idx = base + j;
        if (idx < N) {
            g_off[idx] = pos;
            g_cur[idx] = pos;
            pos += c[j];
        }
    }
    if (blockIdx.x == 0 && t == 0) g_off[N] = E;
}

// ---------------------------------------------------------------------------
// Permute edges into CSR order
// ---------------------------------------------------------------------------
__global__ void permute_kernel(const int* __restrict__ src,
                               const int* __restrict__ dst,
                               const float* __restrict__ val, int E) {
    int e = blockIdx.x * blockDim.x + threadIdx.x;
    if (e < E) {
        int d = dst[e];
        int p = atomicAdd(&g_cur[d], 1);
        g_esrc[p] = src[e];
        g_eval[p] = val[e];
    }
}

// ---------------------------------------------------------------------------
// HMMA helpers
// ---------------------------------------------------------------------------
__device__ __forceinline__ uint32_t pk2(float lo, float hi) {
    uint32_t r;
    asm("cvt.rn.bf16x2.f32 %0, %1, %2;" : "=r"(r) : "f"(hi), "f"(lo));
    return r;
}

__device__ __forceinline__ void mma16816(float* c, uint32_t a0, uint32_t a1,
                                         uint32_t a2, uint32_t a3,
                                         uint32_t b0, uint32_t b1) {
    asm volatile(
        "mma.sync.aligned.m16n8k16.row.col.f32.bf16.bf16.f32 "
        "{%0,%1,%2,%3}, {%4,%5,%6,%7}, {%8,%9}, {%0,%1,%2,%3};"
        : "+f"(c[0]), "+f"(c[1]), "+f"(c[2]), "+f"(c[3])
        : "r"(a0), "r"(a1), "r"(a2), "r"(a3), "r"(b0), "r"(b1));
}

// ---------------------------------------------------------------------------
// Fused SpMM-gather + dense GEMM (mma.sync bf16, 3-way split):
//   LE[r] = sum_{e in CSR(r)} val[e] * feats[src[e]]   (computed in-kernel)
//   out = (LE+feats)@W1^T + (LE*feats)@W2^T + (b1+b2)
// Persistent, 1 CTA/SM, 256 threads (8 warps: 2x4 m/n grid), 64-row tiles.
// ---------------------------------------------------------------------------
#define APAD 136   // padded row length (elems) -> conflict-free fragment LDS
#define WPAD 136

#define OFF_AH  0
#define OFF_AL  (OFF_AH + 64 * APAD * 2)
#define OFF_EH  (OFF_AL + 64 * APAD * 2)
#define OFF_EL  (OFF_EH + 64 * APAD * 2)
#define OFF_W1H (OFF_EL + 64 * APAD * 2)
#define OFF_W1L (OFF_W1H + 128 * WPAD * 2)
#define OFF_W2H (OFF_W1L + 128 * WPAD * 2)
#define OFF_W2L (OFF_W2H + 128 * WPAD * 2)
#define OFF_BIAS (OFF_W2L + 128 * WPAD * 2)
#define SMEM_TOTAL_MM (OFF_BIAS + 128 * 4)

__global__ void __launch_bounds__(256, 1)
fused_kernel(const float* __restrict__ feats,
             const float* __restrict__ W1, const float* __restrict__ b1,
             const float* __restrict__ W2, const float* __restrict__ b2,
             float* __restrict__ out, int N, int nTiles) {
    extern __shared__ char smem[];

    int tid = threadIdx.x;
    int wid = tid >> 5;
    int lane = tid & 31;
    int wm = wid & 1;        // 0..1 : 32-row slice (MMA)
    int wn = wid >> 1;       // 0..3 : 32-col slice (MMA)
    int grp = lane >> 2;     // 0..7
    int quad = lane & 3;     // 0..3

    // ---- one-time: split W1/W2 into bf16 hi/lo in smem; bias ----
    for (int i = tid; i < FDIM * FDIM; i += 256) {
        int n = i >> 7;
        int k = i & 127;
        float w1 = W1[i];
        float w2 = W2[i];
        uint32_t h1 = pk2(w1, 0.f) & 0xFFFFu;
        uint32_t h2 = pk2(w2, 0.f) & 0xFFFFu;
        float r1 = w1 - __uint_as_float(h1 << 16);
        float r2 = w2 - __uint_as_float(h2 << 16);
        uint32_t l1 = pk2(r1, 0.f) & 0xFFFFu;
        uint32_t l2 = pk2(r2, 0.f) & 0xFFFFu;
        size_t o = (size_t)(n * WPAD + k) * 2;
        *(uint16_t*)(smem + OFF_W1H + o) = (uint16_t)h1;
        *(uint16_t*)(smem + OFF_W1L + o) = (uint16_t)l1;
        *(uint16_t*)(smem + OFF_W2H + o) = (uint16_t)h2;
        *(uint16_t*)(smem + OFF_W2L + o) = (uint16_t)l2;
    }
    for (int i = tid; i < FDIM; i += 256)
        *(float*)(smem + OFF_BIAS + i * 4) = b1[i] + b2[i];
    __syncthreads();

    float bv[4][2];
#pragma unroll
    for (int j = 0; j < 4; ++j) {
        int col = wn * 32 + j * 8 + quad * 2;
        bv[j][0] = *(float*)(smem + OFF_BIAS + col * 4);
        bv[j][1] = *(float*)(smem + OFF_BIAS + (col + 1) * 4);
    }

    for (int tile = blockIdx.x; tile < nTiles; tile += gridDim.x) {
        int row0 = tile << 6;

        // ---- fused gather + convert: warp w owns rows w*8 .. w*8+7 ----
        // Lane owns float4 chunk (k = lane*4 .. lane*4+3).
#pragma unroll 1
        for (int rr = 0; rr < 8; ++rr) {
            int r = wid * 8 + rr;
            int row = row0 + r;

            float4 acc = make_float4(0.f, 0.f, 0.f, 0.f);
            float4 ft = acc;
            if (row < N) {
                ft = *(const float4*)&feats[(size_t)row * FDIM + lane * 4];
                int start = g_off[row];
                int end = g_off[row + 1];
                for (int base = start; base < end; base += 32) {
                    int n = end - base;
                    if (n > 32) n = 32;
                    int s = 0;
                    float v = 0.f;
                    if (lane < n) {
                        s = g_esrc[base + lane];
                        v = g_eval[base + lane];
                    }
#pragma unroll 8
                    for (int j = 0; j < n; ++j) {
                        int sj = __shfl_sync(0xffffffff, s, j);
                        float vj = __shfl_sync(0xffffffff, v, j);
                        float4 f = *(const float4*)&feats[(size_t)sj * FDIM + lane * 4];
                        acc.x += vj * f.x;
                        acc.y += vj * f.y;
                        acc.z += vj * f.z;
                        acc.w += vj * f.w;
                    }
                }
            }

            float a0 = acc.x + ft.x, a1 = acc.y + ft.y;
            float a2 = acc.z + ft.z, a3 = acc.w + ft.w;
            float e0 = acc.x * ft.x, e1 = acc.y * ft.y;
            float e2 = acc.z * ft.z, e3 = acc.w * ft.w;

            size_t o = (size_t)(r * APAD + lane * 4) * 2;

            uint32_t ah01 = pk2(a0, a1), ah23 = pk2(a2, a3);
            float ar0 = a0 - __uint_as_float(ah01 << 16);
            float ar1 = a1 - __uint_as_float(ah01 & 0xFFFF0000u);
            float ar2 = a2 - __uint_as_float(ah23 << 16);
            float ar3 = a3 - __uint_as_float(ah23 & 0xFFFF0000u);
            *(uint2*)(smem + OFF_AH + o) = make_uint2(ah01, ah23);
            *(uint2*)(smem + OFF_AL + o) = make_uint2(pk2(ar0, ar1), pk2(ar2, ar3));

            uint32_t eh01 = pk2(e0, e1), eh23 = pk2(e2, e3);
            float er0 = e0 - __uint_as_float(eh01 << 16);
            float er1 = e1 - __uint_as_float(eh01 & 0xFFFF0000u);
            float er2 = e2 - __uint_as_float(eh23 << 16);
            float er3 = e3 - __uint_as_float(eh23 & 0xFFFF0000u);
            *(uint2*)(smem + OFF_EH + o) = make_uint2(eh01, eh23);
            *(uint2*)(smem + OFF_EL + o) = make_uint2(pk2(er0, er1), pk2(er2, er3));
        }
        __syncthreads();

        // ---- MMA mainloop (R5 scheme: direct LDS fragments) ----
        float acc[2][4][4];   // [m-tile][n-tile][frag]
#pragma unroll
        for (int mt = 0; mt < 2; ++mt)
#pragma unroll
            for (int nt = 0; nt < 4; ++nt)
#pragma unroll
                for (int f = 0; f < 4; ++f) acc[mt][nt][f] = 0.f;

        const int aoff[6] = {OFF_AH, OFF_AL, OFF_AH, OFF_EH, OFF_EL, OFF_EH};
        const int woff[6] = {OFF_W1H, OFF_W1H, OFF_W1L, OFF_W2H, OFF_W2H, OFF_W2L};

#pragma unroll
        for (int sg = 0; sg < 6; ++sg) {
            const char* sA = smem + aoff[sg];
            const char* sW = smem + woff[sg];
#pragma unroll
            for (int ks = 0; ks < 8; ++ks) {
                int kb = ks * 16 + quad * 2;
                uint32_t b[4][2];
#pragma unroll
                for (int nt = 0; nt < 4; ++nt) {
                    int n = wn * 32 + nt * 8 + grp;
                    b[nt][0] = *(const uint32_t*)(sW + (size_t)(n * WPAD + kb) * 2);
                    b[nt][1] = *(const uint32_t*)(sW + (size_t)(n * WPAD + kb + 8) * 2);
                }
#pragma unroll
                for (int mt = 0; mt < 2; ++mt) {
                    int rA = wm * 32 + mt * 16 + grp;
                    uint32_t a0 = *(const uint32_t*)(sA + (size_t)(rA * APAD + kb) * 2);
                    uint32_t a1 = *(const uint32_t*)(sA + (size_t)((rA + 8) * APAD + kb) * 2);
                    uint32_t a2 = *(const uint32_t*)(sA + (size_t)(rA * APAD + kb + 8) * 2);
                    uint32_t a3 = *(const uint32_t*)(sA + (size_t)((rA + 8) * APAD + kb + 8) * 2);
#pragma unroll
                    for (int nt = 0; nt < 4; ++nt)
                        mma16816(acc[mt][nt], a0, a1, a2, a3, b[nt][0], b[nt][1]);
                }
            }
        }

        // ---- epilogue: acc + bias -> out ----
#pragma unroll
        for (int mt = 0; mt < 2; ++mt) {
            int r_lo = row0 + wm * 32 + mt * 16 + grp;
            int r_hi = r_lo + 8;
#pragma unroll
            for (int nt = 0; nt < 4; ++nt) {
                int col = wn * 32 + nt * 8 + quad * 2;
                if (r_lo < N) {
                    float2 o;
                    o.x = acc[mt][nt][0] + bv[nt][0];
                    o.y = acc[mt][nt][1] + bv[nt][1];
                    *(float2*)&out[(size_t)r_lo * FDIM + col] = o;
                }
                if (r_hi < N) {
                    float2 o;
                    o.x = acc[mt][nt][2] + bv[nt][0];
                    o.y = acc[mt][nt][3] + bv[nt][1];
                    *(float2*)&out[(size_t)r_hi * FDIM + col] = o;
                }
            }
        }
        __syncthreads();
    }
}

// ---------------------------------------------------------------------------
extern "C" void kernel_launch(void* const* d_in, const int* in_sizes, int n_in,
                              void* d_out, int out_size) {
    const int*   src   = (const int*)d_in[0];
    const int*   dst   = (const int*)d_in[1];
    const float* val   = (const float*)d_in[2];
    const float* feats = (const float*)d_in[3];
    const float* W1    = (const float*)d_in[4];
    const float* b1    = (const float*)d_in[5];
    const float* W2    = (const float*)d_in[6];
    const float* b2    = (const float*)d_in[7];
    float* out = (float*)d_out;

    int E = in_sizes[0];
    int N = in_sizes[3] / FDIM;
    int nseg = (N + SEG - 1) / SEG;
    int nTiles = (N + 63) / 64;

    cudaFuncSetAttribute(fused_kernel,
                         cudaFuncAttributeMaxDynamicSharedMemorySize,
                         SMEM_TOTAL_MM);

    zero_cnt_kernel<<<(N + 255) / 256, 256>>>(N);
    hist_kernel<<<(E + 255) / 256, 256>>>(dst, E);
    scan1_kernel<<<nseg, 256>>>(N);
    scan3_kernel<<<nseg, 256>>>(N, E, nseg);
    permute_kernel<<<(E + 255) / 256, 256>>>(src, dst, val, E);

    int grid = nTiles < 148 ? nTiles : 148;
    fused_kernel<<<grid, 256, SMEM_TOTAL_MM>>>(feats, W1, b1, W2, b2, out,
                                               N, nTiles);
}

// round 8
// speedup vs baseline: 1.6475x; 1.6475x over previous
#include <cuda_runtime.h>
#include <cuda_bf16.h>
#include <cstdint>

#define FDIM 128
#define MAXN 100000
#define MAXE 1600000
#define SEG 1024
#define MAXSEG 128

// ---------------------------------------------------------------------------
// Scratch
// ---------------------------------------------------------------------------
__device__ float g_LE[MAXN * FDIM];
__device__ int   g_cnt[MAXN];     // zero at module load; re-zeroed by permute
__device__ int   g_off[MAXN + 1];
__device__ int   g_cur[MAXN];
__device__ int   g_bsum[MAXSEG];
__device__ int   g_esrc[MAXE];
__device__ float g_eval[MAXE];

// ---------------------------------------------------------------------------
// Histogram of dst
// ---------------------------------------------------------------------------
__global__ void hist_kernel(const int* __restrict__ dst, int E) {
    int e = blockIdx.x * blockDim.x + threadIdx.x;
    if (e < E) atomicAdd(&g_cnt[dst[e]], 1);
}

// ---------------------------------------------------------------------------
// Scan stage 1: per-segment sums
// ---------------------------------------------------------------------------
__global__ void __launch_bounds__(256) scan1_kernel(int N) {
    __shared__ int ssum[256];
    int t = threadIdx.x;
    int base = blockIdx.x * SEG + t * 4;
    int s = 0;
#pragma unroll
    for (int j = 0; j < 4; ++j) {
        int idx = base + j;
        if (idx < N) s += g_cnt[idx];
    }
    ssum[t] = s;
    __syncthreads();
#pragma unroll
    for (int off = 128; off > 0; off >>= 1) {
        if (t < off) ssum[t] += ssum[t + off];
        __syncthreads();
    }
    if (t == 0) g_bsum[blockIdx.x] = ssum[0];
}

// ---------------------------------------------------------------------------
// Scan stage 3 (scan2 folded in): every block scans segment sums locally.
// ---------------------------------------------------------------------------
__global__ void __launch_bounds__(256) scan3_kernel(int N, int E, int nseg) {
    __shared__ int ssum[256];
    __shared__ int sbs[MAXSEG];
    int t = threadIdx.x;

    if (t < MAXSEG) sbs[t] = (t < nseg) ? g_bsum[t] : 0;
    __syncthreads();
#pragma unroll
    for (int off = 1; off < MAXSEG; off <<= 1) {
        int x = 0;
        if (t < MAXSEG && t >= off) x = sbs[t - off];
        __syncthreads();
        if (t < MAXSEG) sbs[t] += x;
        __syncthreads();
    }
    int blockPrefix = (blockIdx.x == 0) ? 0 : sbs[blockIdx.x - 1];

    int base = blockIdx.x * SEG + t * 4;
    int c[4];
    int tsum = 0;
#pragma unroll
    for (int j = 0; j < 4; ++j) {
        int idx = base + j;
        c[j] = (idx < N) ? g_cnt[idx] : 0;
        tsum += c[j];
    }
    ssum[t] = tsum;
    __syncthreads();
#pragma unroll
    for (int off = 1; off < 256; off <<= 1) {
        int x = (t >= off) ? ssum[t - off] : 0;
        __syncthreads();
        ssum[t] += x;
        __syncthreads();
    }
    int excl = ssum[t] - tsum;
    int pos = blockPrefix + excl;
#pragma unroll
    for (int j = 0; j < 4; ++j) {
        int idx = base + j;
        if (idx < N) {
            g_off[idx] = pos;
            g_cur[idx] = pos;
            pos += c[j];
        }
    }
    if (blockIdx.x == 0 && t == 0) g_off[N] = E;
}

// ---------------------------------------------------------------------------
// Permute edges into CSR order; also re-zero g_cnt for the next call
// (g_cnt was fully consumed by scan1/scan3, which precede on this stream).
// ---------------------------------------------------------------------------
__global__ void permute_kernel(const int* __restrict__ src,
                               const int* __restrict__ dst,
                               const float* __restrict__ val, int E, int N) {
    int e = blockIdx.x * blockDim.x + threadIdx.x;
    if (e < N) g_cnt[e] = 0;
    if (e < E) {
        int d = dst[e];
        int p = atomicAdd(&g_cur[d], 1);
        g_esrc[p] = src[e];
        g_eval[p] = val[e];
    }
}

// ---------------------------------------------------------------------------
// Gather: one warp per node.  LE[n] = sum_e val[e] * feats[src[e]]
// ---------------------------------------------------------------------------
__global__ void __launch_bounds__(256)
gather_kernel(const float* __restrict__ feats, int N) {
    int warp = (blockIdx.x << 3) + (threadIdx.x >> 5);
    if (warp >= N) return;
    int lane = threadIdx.x & 31;
    int start = g_off[warp];
    int end = g_off[warp + 1];

    float4 acc = make_float4(0.f, 0.f, 0.f, 0.f);
    for (int base = start; base < end; base += 32) {
        int n = end - base;
        if (n > 32) n = 32;
        int s = 0;
        float v = 0.f;
        if (lane < n) {
            s = g_esrc[base + lane];
            v = g_eval[base + lane];
        }
#pragma unroll 4
        for (int j = 0; j < n; ++j) {
            int sj = __shfl_sync(0xffffffff, s, j);
            float vj = __shfl_sync(0xffffffff, v, j);
            float4 f = *reinterpret_cast<const float4*>(
                &feats[(long long)sj * FDIM + lane * 4]);
            acc.x += vj * f.x;
            acc.y += vj * f.y;
            acc.z += vj * f.z;
            acc.w += vj * f.w;
        }
    }
    *reinterpret_cast<float4*>(&g_LE[(long long)warp * FDIM + lane * 4]) = acc;
}

// ---------------------------------------------------------------------------
// HMMA helpers
// ---------------------------------------------------------------------------
__device__ __forceinline__ uint32_t pk2(float lo, float hi) {
    uint32_t r;
    asm("cvt.rn.bf16x2.f32 %0, %1, %2;" : "=r"(r) : "f"(hi), "f"(lo));
    return r;
}

__device__ __forceinline__ void mma16816(float* c, uint32_t a0, uint32_t a1,
                                         uint32_t a2, uint32_t a3,
                                         uint32_t b0, uint32_t b1) {
    asm volatile(
        "mma.sync.aligned.m16n8k16.row.col.f32.bf16.bf16.f32 "
        "{%0,%1,%2,%3}, {%4,%5,%6,%7}, {%8,%9}, {%0,%1,%2,%3};"
        : "+f"(c[0]), "+f"(c[1]), "+f"(c[2]), "+f"(c[3])
        : "r"(a0), "r"(a1), "r"(a2), "r"(a3), "r"(b0), "r"(b1));
}

// ---------------------------------------------------------------------------
// Fused GEMM via mma.sync bf16 (3-way split), K=256 concat ([a|e] x [W1|W2]).
// Direct per-lane LDS fragment loads (R5 scheme) on a 528B row stride:
// stride = 132 words, 132 mod 32 = 4 -> all fragment LDS are conflict-free
// (R5's 136-elem stride had a 2-way conflict: 8*4 ≡ 0 mod 32).
// Persistent, 1 CTA/SM, 256 threads (8 warps: 2x4 m/n grid), 64-row tiles.
// ---------------------------------------------------------------------------
#define APAD 264                 // padded row length (elems): 528B = 132 words
#define ASTRIDE (APAD * 2)       // bytes

#define OFF_AH   0
#define OFF_AL   (OFF_AH + 64 * ASTRIDE)       // 33792
#define OFF_WH   (OFF_AL + 64 * ASTRIDE)       // 67584
#define OFF_WL   (OFF_WH + 128 * ASTRIDE)      // 135168
#define OFF_BIAS (OFF_WL + 128 * ASTRIDE)      // 202752
#define SMEM_TOTAL_MM (OFF_BIAS + 128 * 4)     // 203264

__global__ void __launch_bounds__(256, 1)
gemm_mm_kernel(const float* __restrict__ feats,
               const float* __restrict__ W1, const float* __restrict__ b1,
               const float* __restrict__ W2, const float* __restrict__ b2,
               float* __restrict__ out, int N, int nTiles) {
    extern __shared__ char smem[];

    int tid = threadIdx.x;
    int wid = tid >> 5;
    int lane = tid & 31;
    int wm = wid & 1;        // 0..1 : 32-row slice
    int wn = wid >> 1;       // 0..3 : 32-col slice
    int grp = lane >> 2;     // 0..7
    int quad = lane & 3;     // 0..3

    // ---- one-time: split W1/W2 into bf16 hi/lo (K-concat layout); bias ----
    for (int i = tid; i < FDIM * FDIM; i += 256) {
        int n = i >> 7;
        int k = i & 127;
        float w1 = W1[i];
        float w2 = W2[i];
        uint32_t h1 = pk2(w1, 0.f) & 0xFFFFu;
        uint32_t h2 = pk2(w2, 0.f) & 0xFFFFu;
        float r1 = w1 - __uint_as_float(h1 << 16);
        float r2 = w2 - __uint_as_float(h2 << 16);
        uint32_t l1 = pk2(r1, 0.f) & 0xFFFFu;
        uint32_t l2 = pk2(r2, 0.f) & 0xFFFFu;
        size_t o1 = (size_t)n * ASTRIDE + (size_t)k * 2;   // W1 at k
        size_t o2 = o1 + 256;                              // W2 at k+128
        *(uint16_t*)(smem + OFF_WH + o1) = (uint16_t)h1;
        *(uint16_t*)(smem + OFF_WL + o1) = (uint16_t)l1;
        *(uint16_t*)(smem + OFF_WH + o2) = (uint16_t)h2;
        *(uint16_t*)(smem + OFF_WL + o2) = (uint16_t)l2;
    }
    for (int i = tid; i < FDIM; i += 256)
        *(float*)(smem + OFF_BIAS + i * 4) = b1[i] + b2[i];
    __syncthreads();

    float bv[4][2];
#pragma unroll
    for (int j = 0; j < 4; ++j) {
        int col = wn * 32 + j * 8 + quad * 2;
        bv[j][0] = *(float*)(smem + OFF_BIAS + col * 4);
        bv[j][1] = *(float*)(smem + OFF_BIAS + (col + 1) * 4);
    }

    for (int tile = blockIdx.x; tile < nTiles; tile += gridDim.x) {
        int row0 = tile << 6;

        // ---- convert 64x128 (LE,feats) -> [a|e] hi/lo bf16 smem tiles ----
#pragma unroll
        for (int i = 0; i < 8; ++i) {
            int chunk = tid + i * 256;       // 0..2047
            int r = chunk >> 5;              // 0..63
            int k = (chunk & 31) << 2;       // 0..124
            int row = row0 + r;
            float4 le = make_float4(0.f, 0.f, 0.f, 0.f);
            float4 ft = le;
            if (row < N) {
                le = *(const float4*)&g_LE[(size_t)row * FDIM + k];
                ft = *(const float4*)&feats[(size_t)row * FDIM + k];
            }
            float a0 = le.x + ft.x, a1 = le.y + ft.y;
            float a2 = le.z + ft.z, a3 = le.w + ft.w;
            float e0 = le.x * ft.x, e1 = le.y * ft.y;
            float e2 = le.z * ft.z, e3 = le.w * ft.w;

            size_t oa = (size_t)r * ASTRIDE + (size_t)k * 2;   // a at k
            size_t oe = oa + 256;                              // e at k+128

            uint32_t ah01 = pk2(a0, a1), ah23 = pk2(a2, a3);
            float ar0 = a0 - __uint_as_float(ah01 << 16);
            float ar1 = a1 - __uint_as_float(ah01 & 0xFFFF0000u);
            float ar2 = a2 - __uint_as_float(ah23 << 16);
            float ar3 = a3 - __uint_as_float(ah23 & 0xFFFF0000u);
            *(uint2*)(smem + OFF_AH + oa) = make_uint2(ah01, ah23);
            *(uint2*)(smem + OFF_AL + oa) = make_uint2(pk2(ar0, ar1), pk2(ar2, ar3));

            uint32_t eh01 = pk2(e0, e1), eh23 = pk2(e2, e3);
            float er0 = e0 - __uint_as_float(eh01 << 16);
            float er1 = e1 - __uint_as_float(eh01 & 0xFFFF0000u);
            float er2 = e2 - __uint_as_float(eh23 << 16);
            float er3 = e3 - __uint_as_float(eh23 & 0xFFFF0000u);
            *(uint2*)(smem + OFF_AH + oe) = make_uint2(eh01, eh23);
            *(uint2*)(smem + OFF_AL + oe) = make_uint2(pk2(er0, er1), pk2(er2, er3));
        }
        __syncthreads();

        // ---- MMA mainloop: 3 split products x 16 k-steps over K=256 ----
        float acc[2][4][4];
#pragma unroll
        for (int mt = 0; mt < 2; ++mt)
#pragma unroll
            for (int nt = 0; nt < 4; ++nt)
#pragma unroll
                for (int f = 0; f < 4; ++f) acc[mt][nt][f] = 0.f;

        const int aoff[3] = {OFF_AH, OFF_AL, OFF_AH};
        const int woff[3] = {OFF_WH, OFF_WH, OFF_WL};

#pragma unroll
        for (int sg = 0; sg < 3; ++sg) {
            const char* sA = smem + aoff[sg];
            const char* sW = smem + woff[sg];
#pragma unroll
            for (int ks = 0; ks < 16; ++ks) {
                int kb = ks * 16 + quad * 2;
                uint32_t b[4][2];
#pragma unroll
                for (int nt = 0; nt < 4; ++nt) {
                    int n = wn * 32 + nt * 8 + grp;
                    b[nt][0] = *(const uint32_t*)(sW + (size_t)n * ASTRIDE + (size_t)kb * 2);
                    b[nt][1] = *(const uint32_t*)(sW + (size_t)n * ASTRIDE + (size_t)(kb + 8) * 2);
                }
#pragma unroll
                for (int mt = 0; mt < 2; ++mt) {
                    int rA = wm * 32 + mt * 16 + grp;
                    uint32_t a0 = *(const uint32_t*)(sA + (size_t)rA * ASTRIDE + (size_t)kb * 2);
                    uint32_t a1 = *(const uint32_t*)(sA + (size_t)(rA + 8) * ASTRIDE + (size_t)kb * 2);
                    uint32_t a2 = *(const uint32_t*)(sA + (size_t)rA * ASTRIDE + (size_t)(kb + 8) * 2);
                    uint32_t a3 = *(const uint32_t*)(sA + (size_t)(rA + 8) * ASTRIDE + (size_t)(kb + 8) * 2);
#pragma unroll
                    for (int nt = 0; nt < 4; ++nt)
                        mma16816(acc[mt][nt], a0, a1, a2, a3, b[nt][0], b[nt][1]);
                }
            }
        }

        // ---- epilogue: acc + bias -> out ----
#pragma unroll
        for (int mt = 0; mt < 2; ++mt) {
            int r_lo = row0 + wm * 32 + mt * 16 + grp;
            int r_hi = r_lo + 8;
#pragma unroll
            for (int nt = 0; nt < 4; ++nt) {
                int col = wn * 32 + nt * 8 + quad * 2;
                if (r_lo < N) {
                    float2 o;
                    o.x = acc[mt][nt][0] + bv[nt][0];
                    o.y = acc[mt][nt][1] + bv[nt][1];
                    *(float2*)&out[(size_t)r_lo * FDIM + col] = o;
                }
                if (r_hi < N) {
                    float2 o;
                    o.x = acc[mt][nt][2] + bv[nt][0];
                    o.y = acc[mt][nt][3] + bv[nt][1];
                    *(float2*)&out[(size_t)r_hi * FDIM + col] = o;
                }
            }
        }
        __syncthreads();
    }
}

// ---------------------------------------------------------------------------
extern "C" void kernel_launch(void* const* d_in, const int* in_sizes, int n_in,
                              void* d_out, int out_size) {
    const int*   src   = (const int*)d_in[0];
    const int*   dst   = (const int*)d_in[1];
    const float* val   = (const float*)d_in[2];
    const float* feats = (const float*)d_in[3];
    const float* W1    = (const float*)d_in[4];
    const float* b1    = (const float*)d_in[5];
    const float* W2    = (const float*)d_in[6];
    const float* b2    = (const float*)d_in[7];
    float* out = (float*)d_out;

    int E = in_sizes[0];
    int N = in_sizes[3] / FDIM;
    int nseg = (N + SEG - 1) / SEG;
    int nTiles = (N + 63) / 64;

    cudaFuncSetAttribute(gemm_mm_kernel,
                         cudaFuncAttributeMaxDynamicSharedMemorySize,
                         SMEM_TOTAL_MM);

    // Launch order puts gemm at position 6 so ncu (-s 5 -c 1) profiles it.
    hist_kernel<<<(E + 255) / 256, 256>>>(dst, E);
    scan1_kernel<<<nseg, 256>>>(N);
    scan3_kernel<<<nseg, 256>>>(N, E, nseg);
    permute_kernel<<<(E + 255) / 256, 256>>>(src, dst, val, E, N);
    gather_kernel<<<(N + 7) / 8, 256>>>(feats, N);

    int grid = nTiles < 148 ? nTiles : 148;
    gemm_mm_kernel<<<grid, 256, SMEM_TOTAL_MM>>>(feats, W1, b1, W2, b2, out,
                                                 N, nTiles);
}

// round 9
// speedup vs baseline: 1.7168x; 1.0420x over previous
#include <cuda_runtime.h>
#include <cuda_bf16.h>
#include <cstdint>

#define FDIM 128
#define MAXN 100000
#define MAXE 1600000
#define SEG 1024
#define MAXSEG 128

// ---------------------------------------------------------------------------
// Scratch
// ---------------------------------------------------------------------------
__device__ float g_LE[MAXN * FDIM];
__device__ int   g_cnt[MAXN];     // zero at module load; re-zeroed by permute
__device__ int   g_off[MAXN + 1];
__device__ int   g_cur[MAXN];
__device__ int   g_bsum[MAXSEG];
__device__ int2  g_edge[MAXE];    // packed {src, val-bits}

// ---------------------------------------------------------------------------
// Histogram of dst
// ---------------------------------------------------------------------------
__global__ void hist_kernel(const int* __restrict__ dst, int E) {
    int e = blockIdx.x * blockDim.x + threadIdx.x;
    if (e < E) atomicAdd(&g_cnt[dst[e]], 1);
}

// ---------------------------------------------------------------------------
// Scan stage 1: per-segment sums
// ---------------------------------------------------------------------------
__global__ void __launch_bounds__(256) scan1_kernel(int N) {
    __shared__ int ssum[256];
    int t = threadIdx.x;
    int base = blockIdx.x * SEG + t * 4;
    int s = 0;
#pragma unroll
    for (int j = 0; j < 4; ++j) {
        int idx = base + j;
        if (idx < N) s += g_cnt[idx];
    }
    ssum[t] = s;
    __syncthreads();
#pragma unroll
    for (int off = 128; off > 0; off >>= 1) {
        if (t < off) ssum[t] += ssum[t + off];
        __syncthreads();
    }
    if (t == 0) g_bsum[blockIdx.x] = ssum[0];
}

// ---------------------------------------------------------------------------
// Scan stage 3 (scan2 folded in): every block scans segment sums locally.
// ---------------------------------------------------------------------------
__global__ void __launch_bounds__(256) scan3_kernel(int N, int E, int nseg) {
    __shared__ int ssum[256];
    __shared__ int sbs[MAXSEG];
    int t = threadIdx.x;

    if (t < MAXSEG) sbs[t] = (t < nseg) ? g_bsum[t] : 0;
    __syncthreads();
#pragma unroll
    for (int off = 1; off < MAXSEG; off <<= 1) {
        int x = 0;
        if (t < MAXSEG && t >= off) x = sbs[t - off];
        __syncthreads();
        if (t < MAXSEG) sbs[t] += x;
        __syncthreads();
    }
    int blockPrefix = (blockIdx.x == 0) ? 0 : sbs[blockIdx.x - 1];

    int base = blockIdx.x * SEG + t * 4;
    int c[4];
    int tsum = 0;
#pragma unroll
    for (int j = 0; j < 4; ++j) {
        int idx = base + j;
        c[j] = (idx < N) ? g_cnt[idx] : 0;
        tsum += c[j];
    }
    ssum[t] = tsum;
    __syncthreads();
#pragma unroll
    for (int off = 1; off < 256; off <<= 1) {
        int x = (t >= off) ? ssum[t - off] : 0;
        __syncthreads();
        ssum[t] += x;
        __syncthreads();
    }
    int excl = ssum[t] - tsum;
    int pos = blockPrefix + excl;
#pragma unroll
    for (int j = 0; j < 4; ++j) {
        int idx = base + j;
        if (idx < N) {
            g_off[idx] = pos;
            g_cur[idx] = pos;
            pos += c[j];
        }
    }
    if (blockIdx.x == 0 && t == 0) g_off[N] = E;
}

// ---------------------------------------------------------------------------
// Permute edges into CSR order (packed int2); re-zero g_cnt for next call.
// ---------------------------------------------------------------------------
__global__ void permute_kernel(const int* __restrict__ src,
                               const int* __restrict__ dst,
                               const float* __restrict__ val, int E, int N) {
    int e = blockIdx.x * blockDim.x + threadIdx.x;
    if (e < N) g_cnt[e] = 0;
    if (e < E) {
        int d = dst[e];
        int p = atomicAdd(&g_cur[d], 1);
        g_edge[p] = make_int2(src[e], __float_as_int(val[e]));
    }
}

// ---------------------------------------------------------------------------
// Gather: one warp per node.  LE[n] = sum_e val[e] * feats[src[e]]
// ---------------------------------------------------------------------------
__global__ void __launch_bounds__(256)
gather_kernel(const float* __restrict__ feats, int N) {
    int warp = (blockIdx.x << 3) + (threadIdx.x >> 5);
    if (warp >= N) return;
    int lane = threadIdx.x & 31;
    int start = g_off[warp];
    int end = g_off[warp + 1];

    float4 acc = make_float4(0.f, 0.f, 0.f, 0.f);
    for (int base = start; base < end; base += 32) {
        int n = end - base;
        if (n > 32) n = 32;
        int s = 0;
        float v = 0.f;
        if (lane < n) {
            int2 ev = g_edge[base + lane];
            s = ev.x;
            v = __int_as_float(ev.y);
        }
#pragma unroll 4
        for (int j = 0; j < n; ++j) {
            int sj = __shfl_sync(0xffffffff, s, j);
            float vj = __shfl_sync(0xffffffff, v, j);
            float4 f = *reinterpret_cast<const float4*>(
                &feats[(long long)sj * FDIM + lane * 4]);
            acc.x += vj * f.x;
            acc.y += vj * f.y;
            acc.z += vj * f.z;
            acc.w += vj * f.w;
        }
    }
    *reinterpret_cast<float4*>(&g_LE[(long long)warp * FDIM + lane * 4]) = acc;
}

// ---------------------------------------------------------------------------
// HMMA helpers
// ---------------------------------------------------------------------------
__device__ __forceinline__ uint32_t pk2(float lo, float hi) {
    uint32_t r;
    asm("cvt.rn.bf16x2.f32 %0, %1, %2;" : "=r"(r) : "f"(hi), "f"(lo));
    return r;
}

__device__ __forceinline__ void mma16816(float* c, uint32_t a0, uint32_t a1,
                                         uint32_t a2, uint32_t a3,
                                         uint32_t b0, uint32_t b1) {
    asm volatile(
        "mma.sync.aligned.m16n8k16.row.col.f32.bf16.bf16.f32 "
        "{%0,%1,%2,%3}, {%4,%5,%6,%7}, {%8,%9}, {%0,%1,%2,%3};"
        : "+f"(c[0]), "+f"(c[1]), "+f"(c[2]), "+f"(c[3])
        : "r"(a0), "r"(a1), "r"(a2), "r"(a3), "r"(b0), "r"(b1));
}

// ---------------------------------------------------------------------------
// Fused GEMM via mma.sync bf16 (3-way split) — exact R5 layout/mainloop,
// plus register prefetch of the next tile's LE/feats (convert pipelining).
// Persistent, 1 CTA/SM, 256 threads (8 warps: 2x4 m/n grid), 64-row tiles.
// ---------------------------------------------------------------------------
#define APAD 136
#define WPAD 136

#define OFF_AH  0
#define OFF_AL  (OFF_AH + 64 * APAD * 2)
#define OFF_EH  (OFF_AL + 64 * APAD * 2)
#define OFF_EL  (OFF_EH + 64 * APAD * 2)
#define OFF_W1H (OFF_EL + 64 * APAD * 2)
#define OFF_W1L (OFF_W1H + 128 * WPAD * 2)
#define OFF_W2H (OFF_W1L + 128 * WPAD * 2)
#define OFF_W2L (OFF_W2H + 128 * WPAD * 2)
#define OFF_BIAS (OFF_W2L + 128 * WPAD * 2)
#define SMEM_TOTAL_MM (OFF_BIAS + 128 * 4)

__global__ void __launch_bounds__(256, 1)
gemm_mm_kernel(const float* __restrict__ feats,
               const float* __restrict__ W1, const float* __restrict__ b1,
               const float* __restrict__ W2, const float* __restrict__ b2,
               float* __restrict__ out, int N, int nTiles) {
    extern __shared__ char smem[];

    int tid = threadIdx.x;
    int wid = tid >> 5;
    int lane = tid & 31;
    int wm = wid & 1;        // 0..1 : 32-row slice
    int wn = wid >> 1;       // 0..3 : 32-col slice
    int grp = lane >> 2;     // 0..7
    int quad = lane & 3;     // 0..3

    // ---- one-time: split W1/W2 into bf16 hi/lo in smem; bias ----
    for (int i = tid; i < FDIM * FDIM; i += 256) {
        int n = i >> 7;
        int k = i & 127;
        float w1 = W1[i];
        float w2 = W2[i];
        uint32_t h1 = pk2(w1, 0.f) & 0xFFFFu;
        uint32_t h2 = pk2(w2, 0.f) & 0xFFFFu;
        float r1 = w1 - __uint_as_float(h1 << 16);
        float r2 = w2 - __uint_as_float(h2 << 16);
        uint32_t l1 = pk2(r1, 0.f) & 0xFFFFu;
        uint32_t l2 = pk2(r2, 0.f) & 0xFFFFu;
        size_t o = (size_t)(n * WPAD + k) * 2;
        *(uint16_t*)(smem + OFF_W1H + o) = (uint16_t)h1;
        *(uint16_t*)(smem + OFF_W1L + o) = (uint16_t)l1;
        *(uint16_t*)(smem + OFF_W2H + o) = (uint16_t)h2;
        *(uint16_t*)(smem + OFF_W2L + o) = (uint16_t)l2;
    }
    for (int i = tid; i < FDIM; i += 256)
        *(float*)(smem + OFF_BIAS + i * 4) = b1[i] + b2[i];
    __syncthreads();

    float bv[4][2];
#pragma unroll
    for (int j = 0; j < 4; ++j) {
        int col = wn * 32 + j * 8 + quad * 2;
        bv[j][0] = *(float*)(smem + OFF_BIAS + col * 4);
        bv[j][1] = *(float*)(smem + OFF_BIAS + (col + 1) * 4);
    }

    // Prefetch registers for the convert pipeline.
    float4 pf_le[8], pf_ft[8];

#define LOAD_TILE(T) do {                                                     \
        int row0_ = (T) << 6;                                                 \
        _Pragma("unroll")                                                     \
        for (int i_ = 0; i_ < 8; ++i_) {                                      \
            int chunk_ = tid + i_ * 256;                                      \
            int r_ = chunk_ >> 5;                                             \
            int k_ = (chunk_ & 31) << 2;                                      \
            int row_ = row0_ + r_;                                            \
            if (row_ < N) {                                                   \
                pf_le[i_] = *(const float4*)&g_LE[(size_t)row_ * FDIM + k_];  \
                pf_ft[i_] = *(const float4*)&feats[(size_t)row_ * FDIM + k_]; \
            } else {                                                          \
                pf_le[i_] = make_float4(0.f, 0.f, 0.f, 0.f);                  \
                pf_ft[i_] = pf_le[i_];                                        \
            }                                                                 \
        }                                                                     \
    } while (0)

    if (blockIdx.x < nTiles) LOAD_TILE((int)blockIdx.x);

    for (int tile = blockIdx.x; tile < nTiles; tile += gridDim.x) {
        int row0 = tile << 6;

        // ---- pack prefetched 64x128 (LE,feats) -> ah/al/eh/el bf16 tiles --
#pragma unroll
        for (int i = 0; i < 8; ++i) {
            int chunk = tid + i * 256;
            int r = chunk >> 5;
            int k = (chunk & 31) << 2;
            float4 le = pf_le[i];
            float4 ft = pf_ft[i];
            float a0 = le.x + ft.x, a1 = le.y + ft.y;
            float a2 = le.z + ft.z, a3 = le.w + ft.w;
            float e0 = le.x * ft.x, e1 = le.y * ft.y;
            float e2 = le.z * ft.z, e3 = le.w * ft.w;

            size_t o = (size_t)(r * APAD + k) * 2;

            uint32_t ah01 = pk2(a0, a1), ah23 = pk2(a2, a3);
            float ar0 = a0 - __uint_as_float(ah01 << 16);
            float ar1 = a1 - __uint_as_float(ah01 & 0xFFFF0000u);
            float ar2 = a2 - __uint_as_float(ah23 << 16);
            float ar3 = a3 - __uint_as_float(ah23 & 0xFFFF0000u);
            *(uint2*)(smem + OFF_AH + o) = make_uint2(ah01, ah23);
            *(uint2*)(smem + OFF_AL + o) = make_uint2(pk2(ar0, ar1), pk2(ar2, ar3));

            uint32_t eh01 = pk2(e0, e1), eh23 = pk2(e2, e3);
            float er0 = e0 - __uint_as_float(eh01 << 16);
            float er1 = e1 - __uint_as_float(eh01 & 0xFFFF0000u);
            float er2 = e2 - __uint_as_float(eh23 << 16);
            float er3 = e3 - __uint_as_float(eh23 & 0xFFFF0000u);
            *(uint2*)(smem + OFF_EH + o) = make_uint2(eh01, eh23);
            *(uint2*)(smem + OFF_EL + o) = make_uint2(pk2(er0, er1), pk2(er2, er3));
        }
        __syncthreads();

        // ---- issue next tile's loads (hidden behind the MMA mainloop) ----
        int nxt = tile + gridDim.x;
        if (nxt < nTiles) LOAD_TILE(nxt);

        // ---- MMA mainloop (R5 scheme: direct LDS fragments) ----
        float acc[2][4][4];
#pragma unroll
        for (int mt = 0; mt < 2; ++mt)
#pragma unroll
            for (int nt = 0; nt < 4; ++nt)
#pragma unroll
                for (int f = 0; f < 4; ++f) acc[mt][nt][f] = 0.f;

        const int aoff[6] = {OFF_AH, OFF_AL, OFF_AH, OFF_EH, OFF_EL, OFF_EH};
        const int woff[6] = {OFF_W1H, OFF_W1H, OFF_W1L, OFF_W2H, OFF_W2H, OFF_W2L};

#pragma unroll
        for (int sg = 0; sg < 6; ++sg) {
            const char* sA = smem + aoff[sg];
            const char* sW = smem + woff[sg];
#pragma unroll
            for (int ks = 0; ks < 8; ++ks) {
                int kb = ks * 16 + quad * 2;
                uint32_t b[4][2];
#pragma unroll
                for (int nt = 0; nt < 4; ++nt) {
                    int n = wn * 32 + nt * 8 + grp;
                    b[nt][0] = *(const uint32_t*)(sW + (size_t)(n * WPAD + kb) * 2);
                    b[nt][1] = *(const uint32_t*)(sW + (size_t)(n * WPAD + kb + 8) * 2);
                }
#pragma unroll
                for (int mt = 0; mt < 2; ++mt) {
                    int rA = wm * 32 + mt * 16 + grp;
                    uint32_t a0 = *(const uint32_t*)(sA + (size_t)(rA * APAD + kb) * 2);
                    uint32_t a1 = *(const uint32_t*)(sA + (size_t)((rA + 8) * APAD + kb) * 2);
                    uint32_t a2 = *(const uint32_t*)(sA + (size_t)(rA * APAD + kb + 8) * 2);
                    uint32_t a3 = *(const uint32_t*)(sA + (size_t)((rA + 8) * APAD + kb + 8) * 2);
#pragma unroll
                    for (int nt = 0; nt < 4; ++nt)
                        mma16816(acc[mt][nt], a0, a1, a2, a3, b[nt][0], b[nt][1]);
                }
            }
        }

        // ---- epilogue: acc + bias -> out ----
#pragma unroll
        for (int mt = 0; mt < 2; ++mt) {
            int r_lo = row0 + wm * 32 + mt * 16 + grp;
            int r_hi = r_lo + 8;
#pragma unroll
            for (int nt = 0; nt < 4; ++nt) {
                int col = wn * 32 + nt * 8 + quad * 2;
                if (r_lo < N) {
                    float2 o;
                    o.x = acc[mt][nt][0] + bv[nt][0];
                    o.y = acc[mt][nt][1] + bv[nt][1];
                    *(float2*)&out[(size_t)r_lo * FDIM + col] = o;
                }
                if (r_hi < N) {
                    float2 o;
                    o.x = acc[mt][nt][2] + bv[nt][0];
                    o.y = acc[mt][nt][3] + bv[nt][1];
                    *(float2*)&out[(size_t)r_hi * FDIM + col] = o;
                }
            }
        }
        __syncthreads();
    }
#undef LOAD_TILE
}

// ---------------------------------------------------------------------------
extern "C" void kernel_launch(void* const* d_in, const int* in_sizes, int n_in,
                              void* d_out, int out_size) {
    const int*   src   = (const int*)d_in[0];
    const int*   dst   = (const int*)d_in[1];
    const float* val   = (const float*)d_in[2];
    const float* feats = (const float*)d_in[3];
    const float* W1    = (const float*)d_in[4];
    const float* b1    = (const float*)d_in[5];
    const float* W2    = (const float*)d_in[6];
    const float* b2    = (const float*)d_in[7];
    float* out = (float*)d_out;

    int E = in_sizes[0];
    int N = in_sizes[3] / FDIM;
    int nseg = (N + SEG - 1) / SEG;
    int nTiles = (N + 63) / 64;

    cudaFuncSetAttribute(gemm_mm_kernel,
                         cudaFuncAttributeMaxDynamicSharedMemorySize,
                         SMEM_TOTAL_MM);

    hist_kernel<<<(E + 255) / 256, 256>>>(dst, E);
    scan1_kernel<<<nseg, 256>>>(N);
    scan3_kernel<<<nseg, 256>>>(N, E, nseg);
    permute_kernel<<<(E + 255) / 256, 256>>>(src, dst, val, E, N);
    gather_kernel<<<(N + 7) / 8, 256>>>(feats, N);

    int grid = nTiles < 148 ? nTiles : 148;
    gemm_mm_kernel<<<grid, 256, SMEM_TOTAL_MM>>>(feats, W1, b1, W2, b2, out,
                                                 N, nTiles);
}

// round 10
// speedup vs baseline: 1.7505x; 1.0196x over previous
#include <cuda_runtime.h>
#include <cuda_bf16.h>
#include <cstdint>

#define FDIM 128
#define MAXN 100000
#define MAXE 1600000
#define SEG 1024
#define MAXSEG 128

// ---------------------------------------------------------------------------
// Scratch
// ---------------------------------------------------------------------------
__device__ float g_LE[MAXN * FDIM];
__device__ int   g_cnt[MAXN];     // zero at module load; re-zeroed by permute
__device__ int   g_off[MAXN + 1];
__device__ int   g_cur[MAXN];
__device__ int   g_bsum[MAXSEG];
__device__ int2  g_edge[MAXE];    // packed {src, val-bits}

// ---------------------------------------------------------------------------
// Histogram of dst
// ---------------------------------------------------------------------------
__global__ void hist_kernel(const int* __restrict__ dst, int E) {
    int e = blockIdx.x * blockDim.x + threadIdx.x;
    if (e < E) atomicAdd(&g_cnt[dst[e]], 1);
}

// ---------------------------------------------------------------------------
// Scan stage 1: per-segment sums
// ---------------------------------------------------------------------------
__global__ void __launch_bounds__(256) scan1_kernel(int N) {
    __shared__ int ssum[256];
    int t = threadIdx.x;
    int base = blockIdx.x * SEG + t * 4;
    int s = 0;
#pragma unroll
    for (int j = 0; j < 4; ++j) {
        int idx = base + j;
        if (idx < N) s += g_cnt[idx];
    }
    ssum[t] = s;
    __syncthreads();
#pragma unroll
    for (int off = 128; off > 0; off >>= 1) {
        if (t < off) ssum[t] += ssum[t + off];
        __syncthreads();
    }
    if (t == 0) g_bsum[blockIdx.x] = ssum[0];
}

// ---------------------------------------------------------------------------
// Scan stage 3 (scan2 folded in): every block scans segment sums locally.
// ---------------------------------------------------------------------------
__global__ void __launch_bounds__(256) scan3_kernel(int N, int E, int nseg) {
    __shared__ int ssum[256];
    __shared__ int sbs[MAXSEG];
    int t = threadIdx.x;

    if (t < MAXSEG) sbs[t] = (t < nseg) ? g_bsum[t] : 0;
    __syncthreads();
#pragma unroll
    for (int off = 1; off < MAXSEG; off <<= 1) {
        int x = 0;
        if (t < MAXSEG && t >= off) x = sbs[t - off];
        __syncthreads();
        if (t < MAXSEG) sbs[t] += x;
        __syncthreads();
    }
    int blockPrefix = (blockIdx.x == 0) ? 0 : sbs[blockIdx.x - 1];

    int base = blockIdx.x * SEG + t * 4;
    int c[4];
    int tsum = 0;
#pragma unroll
    for (int j = 0; j < 4; ++j) {
        int idx = base + j;
        c[j] = (idx < N) ? g_cnt[idx] : 0;
        tsum += c[j];
    }
    ssum[t] = tsum;
    __syncthreads();
#pragma unroll
    for (int off = 1; off < 256; off <<= 1) {
        int x = (t >= off) ? ssum[t - off] : 0;
        __syncthreads();
        ssum[t] += x;
        __syncthreads();
    }
    int excl = ssum[t] - tsum;
    int pos = blockPrefix + excl;
#pragma unroll
    for (int j = 0; j < 4; ++j) {
        int idx = base + j;
        if (idx < N) {
            g_off[idx] = pos;
            g_cur[idx] = pos;
            pos += c[j];
        }
    }
    if (blockIdx.x == 0 && t == 0) g_off[N] = E;
}

// ---------------------------------------------------------------------------
// Permute edges into CSR order (packed int2); re-zero g_cnt for next call.
// ---------------------------------------------------------------------------
__global__ void permute_kernel(const int* __restrict__ src,
                               const int* __restrict__ dst,
                               const float* __restrict__ val, int E, int N) {
    int e = blockIdx.x * blockDim.x + threadIdx.x;
    if (e < N) g_cnt[e] = 0;
    if (e < E) {
        int d = dst[e];
        int p = atomicAdd(&g_cur[d], 1);
        g_edge[p] = make_int2(src[e], __float_as_int(val[e]));
    }
}

// ---------------------------------------------------------------------------
// Gather: one warp per node.  LE[n] = sum_e val[e] * feats[src[e]]
// ---------------------------------------------------------------------------
__global__ void __launch_bounds__(256)
gather_kernel(const float* __restrict__ feats, int N) {
    int warp = (blockIdx.x << 3) + (threadIdx.x >> 5);
    if (warp >= N) return;
    int lane = threadIdx.x & 31;
    int start = g_off[warp];
    int end = g_off[warp + 1];

    float4 acc = make_float4(0.f, 0.f, 0.f, 0.f);
    for (int base = start; base < end; base += 32) {
        int n = end - base;
        if (n > 32) n = 32;
        int s = 0;
        float v = 0.f;
        if (lane < n) {
            int2 ev = g_edge[base + lane];
            s = ev.x;
            v = __int_as_float(ev.y);
        }
#pragma unroll 4
        for (int j = 0; j < n; ++j) {
            int sj = __shfl_sync(0xffffffff, s, j);
            float vj = __shfl_sync(0xffffffff, v, j);
            float4 f = *reinterpret_cast<const float4*>(
                &feats[(long long)sj * FDIM + lane * 4]);
            acc.x += vj * f.x;
            acc.y += vj * f.y;
            acc.z += vj * f.z;
            acc.w += vj * f.w;
        }
    }
    *reinterpret_cast<float4*>(&g_LE[(long long)warp * FDIM + lane * 4]) = acc;
}

// ---------------------------------------------------------------------------
// HMMA helpers
// ---------------------------------------------------------------------------
__device__ __forceinline__ uint32_t pk2(float lo, float hi) {
    uint32_t r;
    asm("cvt.rn.bf16x2.f32 %0, %1, %2;" : "=r"(r) : "f"(hi), "f"(lo));
    return r;
}

__device__ __forceinline__ void mma16816(float* c, uint32_t a0, uint32_t a1,
                                         uint32_t a2, uint32_t a3,
                                         uint32_t b0, uint32_t b1) {
    asm volatile(
        "mma.sync.aligned.m16n8k16.row.col.f32.bf16.bf16.f32 "
        "{%0,%1,%2,%3}, {%4,%5,%6,%7}, {%8,%9}, {%0,%1,%2,%3};"
        : "+f"(c[0]), "+f"(c[1]), "+f"(c[2]), "+f"(c[3])
        : "r"(a0), "r"(a1), "r"(a2), "r"(a3), "r"(b0), "r"(b1));
}

// ---------------------------------------------------------------------------
// Fused GEMM via mma.sync bf16 (3-way split), fragment-reuse mainloop:
// per k-step load {ah, al, wh, wl} fragments ONCE and issue all three
// products (ah*wh + al*wh + ah*wl) -> crossbar bytes cut 96KB -> 64KB/warp.
// Persistent, 1 CTA/SM, 256 threads (8 warps: 2x4 m/n grid), 64-row tiles.
// ---------------------------------------------------------------------------
#define APAD 136
#define WPAD 136

#define OFF_AH  0
#define OFF_AL  (OFF_AH + 64 * APAD * 2)
#define OFF_EH  (OFF_AL + 64 * APAD * 2)
#define OFF_EL  (OFF_EH + 64 * APAD * 2)
#define OFF_W1H (OFF_EL + 64 * APAD * 2)
#define OFF_W1L (OFF_W1H + 128 * WPAD * 2)
#define OFF_W2H (OFF_W1L + 128 * WPAD * 2)
#define OFF_W2L (OFF_W2H + 128 * WPAD * 2)
#define OFF_BIAS (OFF_W2L + 128 * WPAD * 2)
#define SMEM_TOTAL_MM (OFF_BIAS + 128 * 4)

__global__ void __launch_bounds__(256, 1)
gemm_mm_kernel(const float* __restrict__ feats,
               const float* __restrict__ W1, const float* __restrict__ b1,
               const float* __restrict__ W2, const float* __restrict__ b2,
               float* __restrict__ out, int N, int nTiles) {
    extern __shared__ char smem[];

    int tid = threadIdx.x;
    int wid = tid >> 5;
    int lane = tid & 31;
    int wm = wid & 1;        // 0..1 : 32-row slice
    int wn = wid >> 1;       // 0..3 : 32-col slice
    int grp = lane >> 2;     // 0..7
    int quad = lane & 3;     // 0..3

    // ---- one-time: split W1/W2 into bf16 hi/lo in smem; bias ----
    for (int i = tid; i < FDIM * FDIM; i += 256) {
        int n = i >> 7;
        int k = i & 127;
        float w1 = W1[i];
        float w2 = W2[i];
        uint32_t h1 = pk2(w1, 0.f) & 0xFFFFu;
        uint32_t h2 = pk2(w2, 0.f) & 0xFFFFu;
        float r1 = w1 - __uint_as_float(h1 << 16);
        float r2 = w2 - __uint_as_float(h2 << 16);
        uint32_t l1 = pk2(r1, 0.f) & 0xFFFFu;
        uint32_t l2 = pk2(r2, 0.f) & 0xFFFFu;
        size_t o = (size_t)(n * WPAD + k) * 2;
        *(uint16_t*)(smem + OFF_W1H + o) = (uint16_t)h1;
        *(uint16_t*)(smem + OFF_W1L + o) = (uint16_t)l1;
        *(uint16_t*)(smem + OFF_W2H + o) = (uint16_t)h2;
        *(uint16_t*)(smem + OFF_W2L + o) = (uint16_t)l2;
    }
    for (int i = tid; i < FDIM; i += 256)
        *(float*)(smem + OFF_BIAS + i * 4) = b1[i] + b2[i];
    __syncthreads();

    float bv[4][2];
#pragma unroll
    for (int j = 0; j < 4; ++j) {
        int col = wn * 32 + j * 8 + quad * 2;
        bv[j][0] = *(float*)(smem + OFF_BIAS + col * 4);
        bv[j][1] = *(float*)(smem + OFF_BIAS + (col + 1) * 4);
    }

    // Prefetch registers for the convert pipeline.
    float4 pf_le[8], pf_ft[8];

#define LOAD_TILE(T) do {                                                     \
        int row0_ = (T) << 6;                                                 \
        _Pragma("unroll")                                                     \
        for (int i_ = 0; i_ < 8; ++i_) {                                      \
            int chunk_ = tid + i_ * 256;                                      \
            int r_ = chunk_ >> 5;                                             \
            int k_ = (chunk_ & 31) << 2;                                      \
            int row_ = row0_ + r_;                                            \
            if (row_ < N) {                                                   \
                pf_le[i_] = *(const float4*)&g_LE[(size_t)row_ * FDIM + k_];  \
                pf_ft[i_] = *(const float4*)&feats[(size_t)row_ * FDIM + k_]; \
            } else {                                                          \
                pf_le[i_] = make_float4(0.f, 0.f, 0.f, 0.f);                  \
                pf_ft[i_] = pf_le[i_];                                        \
            }                                                                 \
        }                                                                     \
    } while (0)

    if (blockIdx.x < nTiles) LOAD_TILE((int)blockIdx.x);

    for (int tile = blockIdx.x; tile < nTiles; tile += gridDim.x) {
        int row0 = tile << 6;

        // ---- pack prefetched 64x128 (LE,feats) -> ah/al/eh/el bf16 tiles --
#pragma unroll
        for (int i = 0; i < 8; ++i) {
            int chunk = tid + i * 256;
            int r = chunk >> 5;
            int k = (chunk & 31) << 2;
            float4 le = pf_le[i];
            float4 ft = pf_ft[i];
            float a0 = le.x + ft.x, a1 = le.y + ft.y;
            float a2 = le.z + ft.z, a3 = le.w + ft.w;
            float e0 = le.x * ft.x, e1 = le.y * ft.y;
            float e2 = le.z * ft.z, e3 = le.w * ft.w;

            size_t o = (size_t)(r * APAD + k) * 2;

            uint32_t ah01 = pk2(a0, a1), ah23 = pk2(a2, a3);
            float ar0 = a0 - __uint_as_float(ah01 << 16);
            float ar1 = a1 - __uint_as_float(ah01 & 0xFFFF0000u);
            float ar2 = a2 - __uint_as_float(ah23 << 16);
            float ar3 = a3 - __uint_as_float(ah23 & 0xFFFF0000u);
            *(uint2*)(smem + OFF_AH + o) = make_uint2(ah01, ah23);
            *(uint2*)(smem + OFF_AL + o) = make_uint2(pk2(ar0, ar1), pk2(ar2, ar3));

            uint32_t eh01 = pk2(e0, e1), eh23 = pk2(e2, e3);
            float er0 = e0 - __uint_as_float(eh01 << 16);
            float er1 = e1 - __uint_as_float(eh01 & 0xFFFF0000u);
            float er2 = e2 - __uint_as_float(eh23 << 16);
            float er3 = e3 - __uint_as_float(eh23 & 0xFFFF0000u);
            *(uint2*)(smem + OFF_EH + o) = make_uint2(eh01, eh23);
            *(uint2*)(smem + OFF_EL + o) = make_uint2(pk2(er0, er1), pk2(er2, er3));
        }
        __syncthreads();

        // ---- issue next tile's loads (hidden behind the MMA mainloop) ----
        int nxt = tile + gridDim.x;
        if (nxt < nTiles) LOAD_TILE(nxt);

        // ---- MMA mainloop: 2 phases x 8 k-steps, fragments loaded once ----
        float acc[2][4][4];
#pragma unroll
        for (int mt = 0; mt < 2; ++mt)
#pragma unroll
            for (int nt = 0; nt < 4; ++nt)
#pragma unroll
                for (int f = 0; f < 4; ++f) acc[mt][nt][f] = 0.f;

        const int aoffH[2] = {OFF_AH, OFF_EH};
        const int aoffL[2] = {OFF_AL, OFF_EL};
        const int woffH[2] = {OFF_W1H, OFF_W2H};
        const int woffL[2] = {OFF_W1L, OFF_W2L};

#pragma unroll
        for (int ph = 0; ph < 2; ++ph) {
            const char* sAH = smem + aoffH[ph];
            const char* sAL = smem + aoffL[ph];
            const char* sWH = smem + woffH[ph];
            const char* sWL = smem + woffL[ph];
#pragma unroll
            for (int ks = 0; ks < 8; ++ks) {
                int kb = ks * 16 + quad * 2;
                // B fragments (hi and lo), 4 n-tiles x 2 regs each
                uint32_t bh[4][2], bl[4][2];
#pragma unroll
                for (int nt = 0; nt < 4; ++nt) {
                    int n = wn * 32 + nt * 8 + grp;
                    size_t o0 = (size_t)(n * WPAD + kb) * 2;
                    size_t o1 = (size_t)(n * WPAD + kb + 8) * 2;
                    bh[nt][0] = *(const uint32_t*)(sWH + o0);
                    bh[nt][1] = *(const uint32_t*)(sWH + o1);
                    bl[nt][0] = *(const uint32_t*)(sWL + o0);
                    bl[nt][1] = *(const uint32_t*)(sWL + o1);
                }
#pragma unroll
                for (int mt = 0; mt < 2; ++mt) {
                    int rA = wm * 32 + mt * 16 + grp;
                    size_t o0 = (size_t)(rA * APAD + kb) * 2;
                    size_t o1 = (size_t)((rA + 8) * APAD + kb) * 2;
                    size_t o2 = (size_t)(rA * APAD + kb + 8) * 2;
                    size_t o3 = (size_t)((rA + 8) * APAD + kb + 8) * 2;
                    uint32_t ah0 = *(const uint32_t*)(sAH + o0);
                    uint32_t ah1 = *(const uint32_t*)(sAH + o1);
                    uint32_t ah2 = *(const uint32_t*)(sAH + o2);
                    uint32_t ah3 = *(const uint32_t*)(sAH + o3);
                    uint32_t al0 = *(const uint32_t*)(sAL + o0);
                    uint32_t al1 = *(const uint32_t*)(sAL + o1);
                    uint32_t al2 = *(const uint32_t*)(sAL + o2);
                    uint32_t al3 = *(const uint32_t*)(sAL + o3);
#pragma unroll
                    for (int nt = 0; nt < 4; ++nt) {
                        mma16816(acc[mt][nt], ah0, ah1, ah2, ah3, bh[nt][0], bh[nt][1]);
                        mma16816(acc[mt][nt], al0, al1, al2, al3, bh[nt][0], bh[nt][1]);
                        mma16816(acc[mt][nt], ah0, ah1, ah2, ah3, bl[nt][0], bl[nt][1]);
                    }
                }
            }
        }

        // ---- epilogue: acc + bias -> out ----
#pragma unroll
        for (int mt = 0; mt < 2; ++mt) {
            int r_lo = row0 + wm * 32 + mt * 16 + grp;
            int r_hi = r_lo + 8;
#pragma unroll
            for (int nt = 0; nt < 4; ++nt) {
                int col = wn * 32 + nt * 8 + quad * 2;
                if (r_lo < N) {
                    float2 o;
                    o.x = acc[mt][nt][0] + bv[nt][0];
                    o.y = acc[mt][nt][1] + bv[nt][1];
                    *(float2*)&out[(size_t)r_lo * FDIM + col] = o;
                }
                if (r_hi < N) {
                    float2 o;
                    o.x = acc[mt][nt][2] + bv[nt][0];
                    o.y = acc[mt][nt][3] + bv[nt][1];
                    *(float2*)&out[(size_t)r_hi * FDIM + col] = o;
                }
            }
        }
        __syncthreads();
    }
#undef LOAD_TILE
}

// ---------------------------------------------------------------------------
extern "C" void kernel_launch(void* const* d_in, const int* in_sizes, int n_in,
                              void* d_out, int out_size) {
    const int*   src   = (const int*)d_in[0];
    const int*   dst   = (const int*)d_in[1];
    const float* val   = (const float*)d_in[2];
    const float* feats = (const float*)d_in[3];
    const float* W1    = (const float*)d_in[4];
    const float* b1    = (const float*)d_in[5];
    const float* W2    = (const float*)d_in[6];
    const float* b2    = (const float*)d_in[7];
    float* out = (float*)d_out;

    int E = in_sizes[0];
    int N = in_sizes[3] / FDIM;
    int nseg = (N + SEG - 1) / SEG;
    int nTiles = (N + 63) / 64;

    cudaFuncSetAttribute(gemm_mm_kernel,
                         cudaFuncAttributeMaxDynamicSharedMemorySize,
                         SMEM_TOTAL_MM);

    hist_kernel<<<(E + 255) / 256, 256>>>(dst, E);
    scan1_kernel<<<nseg, 256>>>(N);
    scan3_kernel<<<nseg, 256>>>(N, E, nseg);
    permute_kernel<<<(E + 255) / 256, 256>>>(src, dst, val, E, N);
    gather_kernel<<<(N + 7) / 8, 256>>>(feats, N);

    int grid = nTiles < 148 ? nTiles : 148;
    gemm_mm_kernel<<<grid, 256, SMEM_TOTAL_MM>>>(feats, W1, b1, W2, b2, out,
                                                 N, nTiles);
}